// round 4
// baseline (speedup 1.0000x reference)
#include <cuda_runtime.h>
#include <math_constants.h>

// KNN min-dist, 9x9 window, C=3, zero-padded.
// Dot-product expansion: d^2 = |t|^2 + (|o|^2 - 2 t.o), q=|o|^2 in the 4th
// float4 lane -> 3 FFMA + 1 FMNMX per shift. TY=3 vertical blocking for
// occupancy (~38 warps/SM), dj fully unrolled for immediate smem addressing.
// Fixed shapes: B=4, C=3, H=256, W=512.

#define BDIM 128
#define TW 32
#define TH 12
#define TY 3
#define HALO 4
#define SW 9

#define B_ 4
#define H_ 256
#define W_ 512
#define HW_ (H_*W_)

#define SH_H (TH + 2*HALO)   // 20
#define SH_W (TW + 2*HALO)   // 40
#define GRID_Y ((H_ + TH - 1) / TH)   // 22 (last tile partial)

__global__ __launch_bounds__(BDIM, 9) void knn_min_kernel(
    const float* __restrict__ tfm, const float* __restrict__ obs,
    float* __restrict__ out)
{
    __shared__ float4 s4[SH_H][SH_W];   // (o0, o1, o2, |o|^2)

    const int b  = blockIdx.z;
    const int x0 = blockIdx.x * TW;
    const int y0 = blockIdx.y * TH;
    const int tid = threadIdx.x;
    const int tx = tid & 31;
    const int ty = tid >> 5;

    const float* obs_b = obs + b * 3 * HW_;
    const float* tfm_b = tfm + b * 3 * HW_;

    // ---- load obs tile (zero-padded halo), q = |o|^2 computed on the fly ----
    for (int idx = tid; idx < SH_H * SH_W; idx += BDIM) {
        int iy = idx / SH_W;
        int ix = idx - iy * SH_W;
        int gy = y0 - HALO + iy;
        int gx = x0 - HALO + ix;
        float v0 = 0.f, v1 = 0.f, v2 = 0.f;
        if (gy >= 0 && gy < H_ && gx >= 0 && gx < W_) {
            int g = gy * W_ + gx;
            v0 = obs_b[g];
            v1 = obs_b[HW_ + g];
            v2 = obs_b[2 * HW_ + g];
        }
        float q = fmaf(v2, v2, fmaf(v1, v1, v0 * v0));
        s4[iy][ix] = make_float4(v0, v1, v2, q);
    }
    __syncthreads();

    // ---- per-pixel constants: nt_c = -2 t_c, tt = |t|^2 ----
    const int ybase = y0 + ty * TY;
    const int xg = x0 + tx;
    float nt0[TY], nt1[TY], nt2[TY], tt[TY], m[TY];
#pragma unroll
    for (int k = 0; k < TY; k++) {
        int yk = ybase + k;
        int yc = yk < H_ ? yk : (H_ - 1);          // clamp on partial last tile
        int g = yc * W_ + xg;
        float a = tfm_b[g];
        float c = tfm_b[HW_ + g];
        float e = tfm_b[2 * HW_ + g];
        nt0[k] = -2.f * a;
        nt1[k] = -2.f * c;
        nt2[k] = -2.f * e;
        tt[k]  = fmaf(e, e, fmaf(c, c, a * a));
        m[k] = CUDART_INF_F;
    }

    const int rbase = ty * TY;

#pragma unroll
    for (int dj = 0; dj < SW; dj++) {
#pragma unroll
        for (int r = 0; r < TY + 8; r++) {
            const float4 v = s4[rbase + r][tx + dj];
#pragma unroll
            for (int k = 0; k < TY; k++) {
                const int di = r - k;
                if (di >= 0 && di < SW) {
                    float e = fmaf(nt0[k], v.x,
                              fmaf(nt1[k], v.y,
                              fmaf(nt2[k], v.z, v.w)));
                    m[k] = fminf(m[k], e);
                }
            }
        }
    }

    float* out_b = out + b * HW_;
#pragma unroll
    for (int k = 0; k < TY; k++) {
        int yk = ybase + k;
        if (yk < H_)
            out_b[yk * W_ + xg] = sqrtf(fmaxf(tt[k] + m[k], 0.f));
    }
}

extern "C" void kernel_launch(void* const* d_in, const int* in_sizes, int n_in,
                              void* d_out, int out_size)
{
    const float* tfm = (const float*)d_in[0];
    const float* obs = (const float*)d_in[1];
    float* out = (float*)d_out;
    (void)in_sizes; (void)n_in; (void)out_size;

    dim3 grid(W_ / TW, GRID_Y, B_);
    dim3 block(BDIM);
    knn_min_kernel<<<grid, block>>>(tfm, obs, out);
}

// round 5
// speedup vs baseline: 1.1098x; 1.1098x over previous
#include <cuda_runtime.h>
#include <math_constants.h>

// KNN min-dist, 9x9 window, C=3, zero-padded.
// d^2 = |t|^2 + (|o|^2 - 2 t.o); (o0,o1,o2,|o|^2) in float4 smem.
// TX=2 x TY=4 register blocking (8 px/thread); even/odd column split keeps
// LDS.128 conflict-free despite stride-2 lane access.
// Fixed shapes: B=4, C=3, H=256, W=512.

#define TW 32
#define TH 32
#define TX 2
#define TY 4
#define HALO 4
#define SW 9

#define B_ 4
#define H_ 256
#define W_ 512
#define HW_ (H_*W_)

#define SH_H (TH + 2*HALO)   // 40 rows
#define SH_W (TW + 2*HALO)   // 40 cols -> 20 even + 20 odd
#define NR (TY + SW - 1)     // 12 rows per column pass

__global__ __launch_bounds__(128, 4) void knn_min_kernel(
    const float* __restrict__ tfm, const float* __restrict__ obs,
    float* __restrict__ out)
{
    __shared__ float4 sE[SH_H][SH_W/2];
    __shared__ float4 sO[SH_H][SH_W/2];

    const int b  = blockIdx.z;
    const int x0 = blockIdx.x * TW;
    const int y0 = blockIdx.y * TH;
    const int txl = threadIdx.x;        // 0..15
    const int ty  = threadIdx.y;        // 0..7
    const int tid = ty * 16 + txl;

    const float* obs_b = obs + b * 3 * HW_;
    const float* tfm_b = tfm + b * 3 * HW_;

    // ---- load obs tile (zero-padded halo), q=|o|^2, even/odd column split ----
    for (int idx = tid; idx < SH_H * SH_W; idx += 128) {
        int iy = idx / SH_W;
        int ix = idx - iy * SH_W;
        int gy = y0 - HALO + iy;
        int gx = x0 - HALO + ix;
        float v0 = 0.f, v1 = 0.f, v2 = 0.f;
        if (gy >= 0 && gy < H_ && gx >= 0 && gx < W_) {
            int g = gy * W_ + gx;
            v0 = obs_b[g];
            v1 = obs_b[HW_ + g];
            v2 = obs_b[2 * HW_ + g];
        }
        float q = fmaf(v2, v2, fmaf(v1, v1, v0 * v0));
        float4 v = make_float4(v0, v1, v2, q);
        if (ix & 1) sO[iy][ix >> 1] = v;
        else        sE[iy][ix >> 1] = v;
    }
    __syncthreads();

    // ---- per-pixel constants: nt = -2t, tt = |t|^2 (8 px per thread) ----
    const int ybase = y0 + ty * TY;
    const int xb = x0 + 2 * txl;        // even, float2-aligned
    float nt0[TY][TX], nt1[TY][TX], nt2[TY][TX], tt[TY][TX], m[TY][TX];
#pragma unroll
    for (int k = 0; k < TY; k++) {
        int g = (ybase + k) * W_ + xb;
        float2 a = *(const float2*)&tfm_b[g];
        float2 c = *(const float2*)&tfm_b[HW_ + g];
        float2 e = *(const float2*)&tfm_b[2 * HW_ + g];
        nt0[k][0] = -2.f * a.x;  nt0[k][1] = -2.f * a.y;
        nt1[k][0] = -2.f * c.x;  nt1[k][1] = -2.f * c.y;
        nt2[k][0] = -2.f * e.x;  nt2[k][1] = -2.f * e.y;
        tt[k][0] = fmaf(e.x, e.x, fmaf(c.x, c.x, a.x * a.x));
        tt[k][1] = fmaf(e.y, e.y, fmaf(c.y, c.y, a.y * a.y));
        m[k][0] = CUDART_INF_F;  m[k][1] = CUDART_INF_F;
    }

    const int rbase = ty * TY;

    // One column vector serves px0 (dj=c) and px1 (dj=c-1).
#define ACC_ROW(vv, r, P0, P1)                                              \
    {                                                                       \
        const float4 v_ = (vv);                                             \
        _Pragma("unroll")                                                   \
        for (int k = 0; k < TY; k++) {                                      \
            if ((r) >= k && (r) <= k + 8) {                                 \
                float e_ = fmaf(nt0[k][0]*0.f, 0.f, 0.f); (void)e_;         \
                if (P0) {                                                   \
                    float d = fmaf(nt0[k][0], v_.x,                         \
                              fmaf(nt1[k][0], v_.y,                         \
                              fmaf(nt2[k][0], v_.z, v_.w)));                \
                    m[k][0] = fminf(m[k][0], d);                            \
                }                                                           \
                if (P1) {                                                   \
                    float d = fmaf(nt0[k][1], v_.x,                         \
                              fmaf(nt1[k][1], v_.y,                        \
                              fmaf(nt2[k][1], v_.z, v_.w)));                \
                    m[k][1] = fminf(m[k][1], d);                            \
                }                                                           \
            }                                                               \
        }                                                                   \
    }

    // Peel c=0: even col E[txl], px0 only (dj=0)
#pragma unroll
    for (int r = 0; r < NR; r++)
        ACC_ROW(sE[rbase + r][txl], r, true, false);

    // Middle cols c=1..8 as (odd, even) pairs: j=0..3 -> cO=2j+1, cE=2j+2
#pragma unroll 1
    for (int j = 0; j < 4; j++) {
#pragma unroll
        for (int r = 0; r < NR; r++)
            ACC_ROW(sO[rbase + r][txl + j], r, true, true);
#pragma unroll
        for (int r = 0; r < NR; r++)
            ACC_ROW(sE[rbase + r][txl + j + 1], r, true, true);
    }

    // Peel c=9: odd col O[txl+4], px1 only (dj=8)
#pragma unroll
    for (int r = 0; r < NR; r++)
        ACC_ROW(sO[rbase + r][txl + 4], r, false, true);

#undef ACC_ROW

    float* out_b = out + b * HW_;
#pragma unroll
    for (int k = 0; k < TY; k++) {
        float2 o;
        o.x = sqrtf(fmaxf(tt[k][0] + m[k][0], 0.f));
        o.y = sqrtf(fmaxf(tt[k][1] + m[k][1], 0.f));
        *(float2*)&out_b[(ybase + k) * W_ + xb] = o;
    }
}

extern "C" void kernel_launch(void* const* d_in, const int* in_sizes, int n_in,
                              void* d_out, int out_size)
{
    const float* tfm = (const float*)d_in[0];
    const float* obs = (const float*)d_in[1];
    float* out = (float*)d_out;
    (void)in_sizes; (void)n_in; (void)out_size;

    dim3 grid(W_ / TW, H_ / TH, B_);   // 16 x 8 x 4 = 512 blocks
    dim3 block(16, 8);
    knn_min_kernel<<<grid, block>>>(tfm, obs, out);
}

// round 6
// speedup vs baseline: 1.1707x; 1.0549x over previous
#include <cuda_runtime.h>
#include <math_constants.h>

// KNN min-dist, 9x9 window, C=3, zero-padded.
// d^2 = |t|^2 + (|o|^2 - 2 t.o), q=|o|^2 in float4.w -> 3 FFMA + 1 FMNMX/shift.
// R3 tile (TY=4, 128 thr, 1024 blocks) + dual min accumulators (even/odd dj)
// to halve the serial FMNMX chain, dj unrolled x2, 64-reg budget.
// Fixed shapes: B=4, C=3, H=256, W=512.

#define BDIM 128
#define TW 32
#define TH 16
#define TY 4
#define HALO 4
#define SW 9

#define B_ 4
#define H_ 256
#define W_ 512
#define HW_ (H_*W_)

#define SH_H (TH + 2*HALO)   // 24
#define SH_W (TW + 2*HALO)   // 40
#define NR (TY + SW - 1)     // 12

__global__ __launch_bounds__(BDIM, 8) void knn_min_kernel(
    const float* __restrict__ tfm, const float* __restrict__ obs,
    float* __restrict__ out)
{
    __shared__ float4 s4[SH_H][SH_W];   // (o0, o1, o2, |o|^2)

    const int b  = blockIdx.z;
    const int x0 = blockIdx.x * TW;
    const int y0 = blockIdx.y * TH;
    const int tid = threadIdx.x;
    const int tx = tid & 31;
    const int ty = tid >> 5;

    const float* obs_b = obs + b * 3 * HW_;
    const float* tfm_b = tfm + b * 3 * HW_;

    // ---- load obs tile (zero-padded halo), q = |o|^2 on the fly ----
    for (int idx = tid; idx < SH_H * SH_W; idx += BDIM) {
        int iy = idx / SH_W;
        int ix = idx - iy * SH_W;
        int gy = y0 - HALO + iy;
        int gx = x0 - HALO + ix;
        float v0 = 0.f, v1 = 0.f, v2 = 0.f;
        if (gy >= 0 && gy < H_ && gx >= 0 && gx < W_) {
            int g = gy * W_ + gx;
            v0 = obs_b[g];
            v1 = obs_b[HW_ + g];
            v2 = obs_b[2 * HW_ + g];
        }
        float q = fmaf(v2, v2, fmaf(v1, v1, v0 * v0));
        s4[iy][ix] = make_float4(v0, v1, v2, q);
    }
    __syncthreads();

    // ---- per-pixel constants: nt_c = -2 t_c, tt = |t|^2 ----
    const int ybase = y0 + ty * TY;
    const int xg = x0 + tx;
    float nt0[TY], nt1[TY], nt2[TY], tt[TY], m0[TY], m1[TY];
#pragma unroll
    for (int k = 0; k < TY; k++) {
        int g = (ybase + k) * W_ + xg;
        float a = tfm_b[g];
        float c = tfm_b[HW_ + g];
        float e = tfm_b[2 * HW_ + g];
        nt0[k] = -2.f * a;
        nt1[k] = -2.f * c;
        nt2[k] = -2.f * e;
        tt[k]  = fmaf(e, e, fmaf(c, c, a * a));
        m0[k] = CUDART_INF_F;
        m1[k] = CUDART_INF_F;
    }

    const int rbase = ty * TY;

    // One dj column pass: accumulate into macc (acc chosen by dj parity).
#define COL_PASS(DJ, MACC)                                                  \
    {                                                                       \
        _Pragma("unroll")                                                   \
        for (int r = 0; r < NR; r++) {                                      \
            const float4 v = s4[rbase + r][tx + (DJ)];                      \
            _Pragma("unroll")                                               \
            for (int k = 0; k < TY; k++) {                                  \
                if (r >= k && r <= k + 8) {                                 \
                    float e = fmaf(nt0[k], v.x,                             \
                              fmaf(nt1[k], v.y,                             \
                              fmaf(nt2[k], v.z, v.w)));                     \
                    MACC[k] = fminf(MACC[k], e);                            \
                }                                                           \
            }                                                               \
        }                                                                   \
    }

#pragma unroll 1
    for (int j = 0; j < 4; j++) {
        COL_PASS(2 * j,     m0)
        COL_PASS(2 * j + 1, m1)
    }
    COL_PASS(8, m0)

#undef COL_PASS

    float* out_b = out + b * HW_;
#pragma unroll
    for (int k = 0; k < TY; k++) {
        float m = fminf(m0[k], m1[k]);
        out_b[(ybase + k) * W_ + xg] = sqrtf(fmaxf(tt[k] + m, 0.f));
    }
}

extern "C" void kernel_launch(void* const* d_in, const int* in_sizes, int n_in,
                              void* d_out, int out_size)
{
    const float* tfm = (const float*)d_in[0];
    const float* obs = (const float*)d_in[1];
    float* out = (float*)d_out;
    (void)in_sizes; (void)n_in; (void)out_size;

    dim3 grid(W_ / TW, H_ / TH, B_);   // 16 x 16 x 4 = 1024 blocks
    dim3 block(BDIM);
    knn_min_kernel<<<grid, block>>>(tfm, obs, out);
}

// round 7
// speedup vs baseline: 1.2829x; 1.0958x over previous
#include <cuda_runtime.h>
#include <math_constants.h>

// KNN min-dist, 9x9 window, C=3, zero-padded.
// d^2 = |t|^2 + (|o|^2 - 2 t.o), q=|o|^2 in float4.w -> 3 FFMA + 1 FMNMX/shift.
// R3 tile (TY=4, 128thr, 1024 blocks) + flattened (dj,r) loop, fully unrolled,
// 2-deep register-rotated load lookahead: LDS and FFMA overlap per-warp instead
// of alternating burst phases. launch_bounds(128,7) -> 73 regs, one full wave.
// Fixed shapes: B=4, C=3, H=256, W=512.

#define BDIM 128
#define TW 32
#define TH 16
#define TY 4
#define HALO 4
#define SW 9

#define B_ 4
#define H_ 256
#define W_ 512
#define HW_ (H_*W_)

#define SH_H (TH + 2*HALO)   // 24
#define SH_W (TW + 2*HALO)   // 40
#define NR (TY + SW - 1)     // 12 rows per column pass
#define NITER (SW * NR)      // 108

__global__ __launch_bounds__(BDIM, 7) void knn_min_kernel(
    const float* __restrict__ tfm, const float* __restrict__ obs,
    float* __restrict__ out)
{
    __shared__ float4 s4[SH_H][SH_W];   // (o0, o1, o2, |o|^2)

    const int b  = blockIdx.z;
    const int x0 = blockIdx.x * TW;
    const int y0 = blockIdx.y * TH;
    const int tid = threadIdx.x;
    const int tx = tid & 31;
    const int ty = tid >> 5;

    const float* obs_b = obs + b * 3 * HW_;
    const float* tfm_b = tfm + b * 3 * HW_;

    // ---- load obs tile (zero-padded halo), q = |o|^2 on the fly ----
    for (int idx = tid; idx < SH_H * SH_W; idx += BDIM) {
        int iy = idx / SH_W;
        int ix = idx - iy * SH_W;
        int gy = y0 - HALO + iy;
        int gx = x0 - HALO + ix;
        float v0 = 0.f, v1 = 0.f, v2 = 0.f;
        if (gy >= 0 && gy < H_ && gx >= 0 && gx < W_) {
            int g = gy * W_ + gx;
            v0 = obs_b[g];
            v1 = obs_b[HW_ + g];
            v2 = obs_b[2 * HW_ + g];
        }
        float q = fmaf(v2, v2, fmaf(v1, v1, v0 * v0));
        s4[iy][ix] = make_float4(v0, v1, v2, q);
    }
    __syncthreads();

    // ---- per-pixel constants: nt_c = -2 t_c, tt = |t|^2 ----
    const int ybase = y0 + ty * TY;
    const int xg = x0 + tx;
    float nt0[TY], nt1[TY], nt2[TY], tt[TY], m0[TY], m1[TY];
#pragma unroll
    for (int k = 0; k < TY; k++) {
        int g = (ybase + k) * W_ + xg;
        float a = tfm_b[g];
        float c = tfm_b[HW_ + g];
        float e = tfm_b[2 * HW_ + g];
        nt0[k] = -2.f * a;
        nt1[k] = -2.f * c;
        nt2[k] = -2.f * e;
        tt[k]  = fmaf(e, e, fmaf(c, c, a * a));
        m0[k] = CUDART_INF_F;
        m1[k] = CUDART_INF_F;
    }

    // Flat base: iteration i -> dj = i/NR, r = i%NR, word offset r*SH_W + dj.
    const float4* base = &s4[ty * TY][tx];
#define OFF(i) (((i) % NR) * SH_W + ((i) / NR))

    float4 buf[3];
    buf[0] = base[OFF(0)];
    buf[1] = base[OFF(1)];

#pragma unroll
    for (int i = 0; i < NITER; i++) {
        if (i + 2 < NITER)
            buf[(i + 2) % 3] = base[OFF(i + 2)];
        const float4 v = buf[i % 3];
        const int dj = i / NR;
        const int r  = i % NR;
#pragma unroll
        for (int k = 0; k < TY; k++) {
            const int di = r - k;
            if (di >= 0 && di < SW) {
                float e = fmaf(nt0[k], v.x,
                          fmaf(nt1[k], v.y,
                          fmaf(nt2[k], v.z, v.w)));
                if (dj & 1) m1[k] = fminf(m1[k], e);
                else        m0[k] = fminf(m0[k], e);
            }
        }
    }
#undef OFF

    float* out_b = out + b * HW_;
#pragma unroll
    for (int k = 0; k < TY; k++) {
        float m = fminf(m0[k], m1[k]);
        out_b[(ybase + k) * W_ + xg] = sqrtf(fmaxf(tt[k] + m, 0.f));
    }
}

extern "C" void kernel_launch(void* const* d_in, const int* in_sizes, int n_in,
                              void* d_out, int out_size)
{
    const float* tfm = (const float*)d_in[0];
    const float* obs = (const float*)d_in[1];
    float* out = (float*)d_out;
    (void)in_sizes; (void)n_in; (void)out_size;

    dim3 grid(W_ / TW, H_ / TH, B_);   // 16 x 16 x 4 = 1024 blocks
    dim3 block(BDIM);
    knn_min_kernel<<<grid, block>>>(tfm, obs, out);
}